// round 16
// baseline (speedup 1.0000x reference)
#include <cuda_runtime.h>

// y = s1 * FWHT( g * FWHT( s2 * x ) ) per token, D = 4096.
// R14 body (proven, 86.2us) + grid-stride loop over token-pairs with
// grid = 4*148 = 592 (one full occupancy wave) to kill wave quantization:
// fixed 4-pairs/CTA ran 2 sequential waves (8 pair-times); grid-stride packs
// the same 4096 pairs into max 7 pair-times per CTA.
//   L0: regs i8-11, lanes i0-4, warps i5-7      (coalesced global I/O)
//   L1: regs i4-7,  lanes {i0-3, i8}, warps i9-11
// sigma(i) = i0_3 | (i4^i8)<<4 | i5_7<<5 | i8<<8 | i9_11<<9

#define DDIM 4096
#define NEG1 0xBF800000BF800000ULL

typedef unsigned long long u64;

__device__ __forceinline__ u64 pk2(float lo, float hi) {
    u64 u; asm("mov.b64 %0,{%1,%2};" : "=l"(u) : "f"(lo), "f"(hi)); return u;
}
__device__ __forceinline__ void up2(u64 u, float& a, float& b) {
    asm("mov.b64 {%0,%1},%2;" : "=f"(a), "=f"(b) : "l"(u));
}
__device__ __forceinline__ u64 add2(u64 a, u64 b) {
    u64 r; asm("add.rn.f32x2 %0,%1,%2;" : "=l"(r) : "l"(a), "l"(b)); return r;
}
__device__ __forceinline__ u64 mul2(u64 a, u64 b) {
    u64 r; asm("mul.rn.f32x2 %0,%1,%2;" : "=l"(r) : "l"(a), "l"(b)); return r;
}
__device__ __forceinline__ u64 fma2(u64 a, u64 b, u64 c) {
    u64 r; asm("fma.rn.f32x2 %0,%1,%2,%3;" : "=l"(r) : "l"(a), "l"(b), "l"(c)); return r;
}
__device__ __forceinline__ void bstep(u64& a, u64& c) {
    u64 s = add2(a, c);
    u64 d = fma2(c, NEG1, a);
    a = s; c = d;
}
__device__ __forceinline__ void bfly4p(u64 U[16]) {
#pragma unroll
    for (int b = 1; b < 16; b <<= 1)
#pragma unroll
        for (int r = 0; r < 16; r++)
            if (!(r & b)) bstep(U[r], U[r | b]);
}

__device__ __forceinline__ float softplus_f(float x) {
    return fmaxf(x, 0.0f) + log1pf(expf(-fabsf(x)));
}

__global__ void __launch_bounds__(256, 4)
whvi_kernel(const float* __restrict__ x,
            const float* __restrict__ s1,
            const float* __restrict__ s2,
            const float* __restrict__ g_mu,
            const float* __restrict__ g_rho,
            const float* __restrict__ eps,
            float* __restrict__ out,
            int n_tokens)
{
    __shared__ u64   sh2[DDIM];    // 32 KB packed exchange buffer (sigma)
    __shared__ float gbuf[DDIM];   // 16 KB g_tilde at sigma (L1-side) addresses

    const int t = threadIdx.x;     // 0..255 ; L0: t = i0-7
    const int l = t & 31;
    const int w = t >> 5;

    // sigma bases:
    //  L0 side: addr(r) = t ^ ((r&1)*0x110) ^ ((r>>1)<<9)   (r = i8-11)
    //  L1 side: addr(r) = rb ^ (r<<4)                       (r = i4-7)
    const int rb = (l & 15) | ((l >> 4) << 4) | ((l >> 4) << 8) | (w << 9);

    // ---- g_tilde once per CTA at sigma L1-side addresses ----
#pragma unroll
    for (int r = 0; r < 16; r++) {
        const int i = (l & 15) | (r << 4) | ((l >> 4) << 8) | (w << 9);
        gbuf[rb ^ (r << 4)] = g_mu[i] + softplus_f(g_rho[i]) * eps[i];
    }
    // visible before first read via pair-0's X1 barriers

    const int npairs = (n_tokens + 1) >> 1;

    for (int pr = blockIdx.x; pr < npairs; pr += gridDim.x) {
        const int tokA = pr << 1;
        const bool hasB = (tokA + 1 < n_tokens);

        const float* __restrict__ xA = x + (size_t)tokA * DDIM;

        // ---- load both tokens, * s2, pack ----  (L0: elem i = t + 256r)
        u64 U[16];
#pragma unroll
        for (int r = 0; r < 16; r++) {
            const int i = t + (r << 8);
            const float s = s2[i];
            const float a = xA[i] * s;
            const float b = hasB ? xA[i + DDIM] * s : 0.0f;
            U[r] = pk2(a, b);
        }

        bfly4p(U);                                  // FWHT1 bits 8-11

        // ---- X1: L0 -> L1 ----
        __syncthreads();                            // WAR vs prev pair X2 reads
#pragma unroll
        for (int r = 0; r < 16; r++)
            sh2[t ^ ((r & 1) * 0x110) ^ ((r >> 1) << 9)] = U[r];
        __syncthreads();
#pragma unroll
        for (int r = 0; r < 16; r++)
            U[r] = sh2[rb ^ (r << 4)];

        bfly4p(U);                                  // FWHT1 bits 4-7

        // ---- FWHT1 shuffles: bits 0-3 (u64-native) ----
#pragma unroll
        for (int s = 0; s < 4; s++) {
            const int m = 1 << s;
            const float sg = (l & m) ? -1.0f : 1.0f;
            const u64 sg2 = pk2(sg, sg);
#pragma unroll
            for (int r = 0; r < 16; r++) {
                const u64 p = __shfl_xor_sync(0xffffffffu, U[r], m);
                U[r] = fma2(U[r], sg2, p);
            }
        }

        // ---- * g_tilde (sigma addresses, conflict-free) ----
#pragma unroll
        for (int r = 0; r < 16; r++) {
            const float g = gbuf[rb ^ (r << 4)];
            U[r] = mul2(U[r], pk2(g, g));
        }

        // ---- FWHT2 shuffles: bits 0-3 ----
#pragma unroll
        for (int s = 0; s < 4; s++) {
            const int m = 1 << s;
            const float sg = (l & m) ? -1.0f : 1.0f;
            const u64 sg2 = pk2(sg, sg);
#pragma unroll
            for (int r = 0; r < 16; r++) {
                const u64 p = __shfl_xor_sync(0xffffffffu, U[r], m);
                U[r] = fma2(U[r], sg2, p);
            }
        }

        bfly4p(U);                                  // FWHT2 bits 4-7

        // ---- X2: L1 -> L0 ----
        __syncthreads();                            // WAR vs X1/g reads
#pragma unroll
        for (int r = 0; r < 16; r++)
            sh2[rb ^ (r << 4)] = U[r];
        __syncthreads();
#pragma unroll
        for (int r = 0; r < 16; r++)
            U[r] = sh2[t ^ ((r & 1) * 0x110) ^ ((r >> 1) << 9)];

        bfly4p(U);                                  // FWHT2 bits 8-11

        // ---- * s1, unpack, store both tokens (coalesced) ----
        float* __restrict__ oA = out + (size_t)tokA * DDIM;
#pragma unroll
        for (int r = 0; r < 16; r++) {
            const int i = t + (r << 8);
            const float s = s1[i];
            float a, b; up2(U[r], a, b);
            oA[i] = a * s;
            if (hasB) oA[i + DDIM] = b * s;
        }
    }
}

extern "C" void kernel_launch(void* const* d_in, const int* in_sizes, int n_in,
                              void* d_out, int out_size)
{
    const float* x     = (const float*)d_in[0];
    const float* s1    = (const float*)d_in[1];
    const float* s2    = (const float*)d_in[2];
    const float* g_mu  = (const float*)d_in[3];
    const float* g_rho = (const float*)d_in[4];
    const float* eps   = (const float*)d_in[5];
    // d_in[6] = H, unused

    float* out = (float*)d_out;
    const int n_tokens = in_sizes[0] / DDIM;
    const int npairs = (n_tokens + 1) / 2;

    int grid = 148 * 4;                 // one full occupancy wave on GB300
    if (grid > npairs) grid = npairs;

    whvi_kernel<<<grid, 256>>>(x, s1, s2, g_mu, g_rho, eps, out, n_tokens);
}

// round 17
// speedup vs baseline: 1.0316x; 1.0316x over previous
#include <cuda_runtime.h>

// y = s1 * FWHT( g * FWHT( s2 * x ) ) per token, D = 4096.
// R15 body (86.2-86.7us) with the two WAR __syncthreads REMOVED:
//   - X2 writes touch exactly the addresses the same thread read at X1
//   - X1 writes (next pair) touch exactly the addresses the same thread
//     read at X2 of the previous pair
//   - gbuf: each thread reads only slots it wrote
// => only the 2 cross-thread RAW barriers per pair remain.
//   L0: regs i8-11, lanes i0-4, warps i5-7      (coalesced global I/O)
//   L1: regs i4-7,  lanes {i0-3, i8}, warps i9-11
// sigma(i) = i0_3 | (i4^i8)<<4 | i5_7<<5 | i8<<8 | i9_11<<9

#define DDIM 4096
#define NEG1 0xBF800000BF800000ULL

typedef unsigned long long u64;

__device__ __forceinline__ u64 pk2(float lo, float hi) {
    u64 u; asm("mov.b64 %0,{%1,%2};" : "=l"(u) : "f"(lo), "f"(hi)); return u;
}
__device__ __forceinline__ void up2(u64 u, float& a, float& b) {
    asm("mov.b64 {%0,%1},%2;" : "=f"(a), "=f"(b) : "l"(u));
}
__device__ __forceinline__ u64 add2(u64 a, u64 b) {
    u64 r; asm("add.rn.f32x2 %0,%1,%2;" : "=l"(r) : "l"(a), "l"(b)); return r;
}
__device__ __forceinline__ u64 mul2(u64 a, u64 b) {
    u64 r; asm("mul.rn.f32x2 %0,%1,%2;" : "=l"(r) : "l"(a), "l"(b)); return r;
}
__device__ __forceinline__ u64 fma2(u64 a, u64 b, u64 c) {
    u64 r; asm("fma.rn.f32x2 %0,%1,%2,%3;" : "=l"(r) : "l"(a), "l"(b), "l"(c)); return r;
}
__device__ __forceinline__ void bstep(u64& a, u64& c) {
    u64 s = add2(a, c);
    u64 d = fma2(c, NEG1, a);
    a = s; c = d;
}
__device__ __forceinline__ void bfly4p(u64 U[16]) {
#pragma unroll
    for (int b = 1; b < 16; b <<= 1)
#pragma unroll
        for (int r = 0; r < 16; r++)
            if (!(r & b)) bstep(U[r], U[r | b]);
}

__device__ __forceinline__ float softplus_f(float x) {
    return fmaxf(x, 0.0f) + log1pf(expf(-fabsf(x)));
}

__global__ void __launch_bounds__(256, 4)
whvi_kernel(const float* __restrict__ x,
            const float* __restrict__ s1,
            const float* __restrict__ s2,
            const float* __restrict__ g_mu,
            const float* __restrict__ g_rho,
            const float* __restrict__ eps,
            float* __restrict__ out,
            int n_tokens)
{
    __shared__ u64   sh2[DDIM];    // 32 KB packed exchange buffer (sigma)
    __shared__ float gbuf[DDIM];   // 16 KB g_tilde at sigma (L1-side) addresses

    const int t = threadIdx.x;     // 0..255 ; L0: t = i0-7
    const int l = t & 31;
    const int w = t >> 5;

    // sigma bases:
    //  L0 side: addr(r) = t ^ ((r&1)*0x110) ^ ((r>>1)<<9)   (r = i8-11)
    //  L1 side: addr(r) = rb ^ (r<<4)                       (r = i4-7)
    const int rb = (l & 15) | ((l >> 4) << 4) | ((l >> 4) << 8) | (w << 9);

    // ---- g_tilde once per CTA at sigma L1-side addresses ----
    // (each thread writes exactly the slots it will read -> no barrier needed)
#pragma unroll
    for (int r = 0; r < 16; r++) {
        const int i = (l & 15) | (r << 4) | ((l >> 4) << 8) | (w << 9);
        gbuf[rb ^ (r << 4)] = g_mu[i] + softplus_f(g_rho[i]) * eps[i];
    }

    const int npairs = (n_tokens + 1) >> 1;

    for (int pr = blockIdx.x; pr < npairs; pr += gridDim.x) {
        const int tokA = pr << 1;
        const bool hasB = (tokA + 1 < n_tokens);

        const float* __restrict__ xA = x + (size_t)tokA * DDIM;

        // ---- load both tokens, * s2, pack ----  (L0: elem i = t + 256r)
        u64 U[16];
#pragma unroll
        for (int r = 0; r < 16; r++) {
            const int i = t + (r << 8);
            const float s = s2[i];
            const float a = xA[i] * s;
            const float b = hasB ? xA[i + DDIM] * s : 0.0f;
            U[r] = pk2(a, b);
        }

        bfly4p(U);                                  // FWHT1 bits 8-11

        // ---- X1: L0 -> L1 ----
        // no WAR barrier: these addresses were last read by THIS thread
        // (they form its X2-read set of the previous pair)
#pragma unroll
        for (int r = 0; r < 16; r++)
            sh2[t ^ ((r & 1) * 0x110) ^ ((r >> 1) << 9)] = U[r];
        __syncthreads();                            // RAW: cross-thread reads
#pragma unroll
        for (int r = 0; r < 16; r++)
            U[r] = sh2[rb ^ (r << 4)];

        bfly4p(U);                                  // FWHT1 bits 4-7

        // ---- FWHT1 shuffles: bits 0-3 (u64-native) ----
#pragma unroll
        for (int s = 0; s < 4; s++) {
            const int m = 1 << s;
            const float sg = (l & m) ? -1.0f : 1.0f;
            const u64 sg2 = pk2(sg, sg);
#pragma unroll
            for (int r = 0; r < 16; r++) {
                const u64 p = __shfl_xor_sync(0xffffffffu, U[r], m);
                U[r] = fma2(U[r], sg2, p);
            }
        }

        // ---- * g_tilde (sigma addresses, conflict-free, thread-private) ----
#pragma unroll
        for (int r = 0; r < 16; r++) {
            const float g = gbuf[rb ^ (r << 4)];
            U[r] = mul2(U[r], pk2(g, g));
        }

        // ---- FWHT2 shuffles: bits 0-3 ----
#pragma unroll
        for (int s = 0; s < 4; s++) {
            const int m = 1 << s;
            const float sg = (l & m) ? -1.0f : 1.0f;
            const u64 sg2 = pk2(sg, sg);
#pragma unroll
            for (int r = 0; r < 16; r++) {
                const u64 p = __shfl_xor_sync(0xffffffffu, U[r], m);
                U[r] = fma2(U[r], sg2, p);
            }
        }

        bfly4p(U);                                  // FWHT2 bits 4-7

        // ---- X2: L1 -> L0 ----
        // no WAR barrier: these addresses are exactly THIS thread's X1-read set
#pragma unroll
        for (int r = 0; r < 16; r++)
            sh2[rb ^ (r << 4)] = U[r];
        __syncthreads();                            // RAW: cross-thread reads
#pragma unroll
        for (int r = 0; r < 16; r++)
            U[r] = sh2[t ^ ((r & 1) * 0x110) ^ ((r >> 1) << 9)];

        bfly4p(U);                                  // FWHT2 bits 8-11

        // ---- * s1, unpack, store both tokens (coalesced) ----
        float* __restrict__ oA = out + (size_t)tokA * DDIM;
#pragma unroll
        for (int r = 0; r < 16; r++) {
            const int i = t + (r << 8);
            const float s = s1[i];
            float a, b; up2(U[r], a, b);
            oA[i] = a * s;
            if (hasB) oA[i + DDIM] = b * s;
        }
    }
}

extern "C" void kernel_launch(void* const* d_in, const int* in_sizes, int n_in,
                              void* d_out, int out_size)
{
    const float* x     = (const float*)d_in[0];
    const float* s1    = (const float*)d_in[1];
    const float* s2    = (const float*)d_in[2];
    const float* g_mu  = (const float*)d_in[3];
    const float* g_rho = (const float*)d_in[4];
    const float* eps   = (const float*)d_in[5];
    // d_in[6] = H, unused

    float* out = (float*)d_out;
    const int n_tokens = in_sizes[0] / DDIM;
    const int npairs = (n_tokens + 1) / 2;

    int grid = 148 * 4;                 // one full occupancy wave on GB300
    if (grid > npairs) grid = npairs;

    whvi_kernel<<<grid, 256>>>(x, s1, s2, g_mu, g_rho, eps, out, n_tokens);
}